// round 5
// baseline (speedup 1.0000x reference)
#include <cuda_runtime.h>
#include <cstdint>

#define GSLAB 262144          // 512*512 floats per k-slab
#define COFF  (50*GSLAB)      // offset of cos slabs
#define AS_F  (2*2*16*64)     // A smem floats: [buf][feat][kk][64]
#define BS_F  (2*2*16*256)    // B smem floats: [buf][feat][kk][256]
#define SMEM_BYTES ((AS_F + BS_F) * 4)

#define AIDX(b,f,kk,m) ((((b)*2+(f))*16+(kk))*64+(m))
#define BIDX(b,f,kk,n) ((((b)*2+(f))*16+(kk))*256+(n))

__device__ __forceinline__ unsigned long long pk2(float v) {
    unsigned long long r; asm("mov.b64 %0, {%1, %1};" : "=l"(r) : "f"(v)); return r;
}
__device__ __forceinline__ float2 upk(unsigned long long v) {
    float2 r; asm("mov.b64 {%0, %1}, %2;" : "=f"(r.x), "=f"(r.y) : "l"(v)); return r;
}
__device__ __forceinline__ void fma2(unsigned long long& d, unsigned long long a, unsigned long long b) {
    asm("fma.rn.f32x2 %0, %1, %2, %0;" : "+l"(d) : "l"(a), "l"(b));
}
__device__ __forceinline__ void cpa16(uint32_t s, const float* g) {
    asm volatile("cp.async.cg.shared.global [%0], [%1], 16;" :: "r"(s), "l"(g));
}

__global__ void init_out_kernel(const float* __restrict__ bias, float* __restrict__ out) {
    int i = blockIdx.x * 256 + threadIdx.x;
    out[i] = bias[i & 511];
}

__global__ void __launch_bounds__(128, 2)
fkan_kernel(const float* __restrict__ x, const float* __restrict__ fc,
            float* __restrict__ out)
{
    extern __shared__ float sm[];
    float* As = sm;
    float* Bs = sm + AS_F;
    const uint32_t bs_sa = (uint32_t)__cvta_generic_to_shared(Bs);

    const int tid = threadIdx.x;
    const int w = tid >> 5, l = tid & 31;

    const int bid    = blockIdx.x;
    const int isplit = bid & 15;             // 16 i-splits of 32
    const int tile   = bid >> 4;             // 64 output tiles
    const int n0     = (tile & 1) * 256;
    const int m0     = (tile >> 1) * 64;

    // state slots: this thread owns (kk=skk, m=smb..smb+7)
    const int skk = tid >> 3;
    const int smb = (tid & 7) << 3;

    // B cp.async mapping: float4 f = r*128+tid -> kk = 2r + (tid>>6), n4 = tid&63
    const int bkk = tid >> 6;
    const int bn4 = tid & 63;

    unsigned long long acc[16][4];
#pragma unroll
    for (int i = 0; i < 16; ++i)
#pragma unroll
        for (int j = 0; j < 4; ++j) acc[i][j] = 0ull;

    for (int ic = 0; ic < 2; ++ic) {
        const int ib = isplit * 32 + ic * 16;

        // ---- base rotation (k=1): s1=sin(pi x), c1=cos(pi x); also initial state ----
        float s1[8], c1[8];
        const float* xp = x + (size_t)(m0 + smb) * 512 + ib + skk;
#pragma unroll
        for (int j = 0; j < 8; ++j) sincospif(__ldg(xp + (size_t)j * 512), &s1[j], &c1[j]);
        *(float4*)&As[AIDX(0,0,skk,smb)]   = make_float4(s1[0],s1[1],s1[2],s1[3]);
        *(float4*)&As[AIDX(0,0,skk,smb+4)] = make_float4(s1[4],s1[5],s1[6],s1[7]);
        *(float4*)&As[AIDX(0,1,skk,smb)]   = make_float4(c1[0],c1[1],c1[2],c1[3]);
        *(float4*)&As[AIDX(0,1,skk,smb+4)] = make_float4(c1[4],c1[5],c1[6],c1[7]);

        // ---- prologue: stage B(k=1) into buf 0 ----
        {
            const float* g0 = fc + (size_t)ib * 512 + n0 + 4 * bn4;
#pragma unroll
            for (int r = 0; r < 8; ++r) {
                int kk = 2 * r + bkk;
                cpa16(bs_sa + BIDX(0,0,kk,4*bn4) * 4, g0 + (size_t)kk * 512);
                cpa16(bs_sa + BIDX(0,1,kk,4*bn4) * 4, g0 + (size_t)kk * 512 + COFF);
            }
            asm volatile("cp.async.commit_group;");
        }

        for (int t = 0; t < 50; ++t) {
            const int cur = t & 1, nxt = cur ^ 1;

            if (t < 49) {
                // advance state: read k=t+1 from As[cur], write k=t+2 to As[nxt]
                float4 ps0 = *(float4*)&As[AIDX(cur,0,skk,smb)];
                float4 ps1 = *(float4*)&As[AIDX(cur,0,skk,smb+4)];
                float4 pc0 = *(float4*)&As[AIDX(cur,1,skk,smb)];
                float4 pc1 = *(float4*)&As[AIDX(cur,1,skk,smb+4)];
                float ps[8] = {ps0.x,ps0.y,ps0.z,ps0.w,ps1.x,ps1.y,ps1.z,ps1.w};
                float pc[8] = {pc0.x,pc0.y,pc0.z,pc0.w,pc1.x,pc1.y,pc1.z,pc1.w};
                float ns[8], nc[8];
#pragma unroll
                for (int j = 0; j < 8; ++j) {
                    ns[j] = fmaf(ps[j], c1[j],  pc[j] * s1[j]);
                    nc[j] = fmaf(pc[j], c1[j], -ps[j] * s1[j]);
                }
                *(float4*)&As[AIDX(nxt,0,skk,smb)]   = make_float4(ns[0],ns[1],ns[2],ns[3]);
                *(float4*)&As[AIDX(nxt,0,skk,smb+4)] = make_float4(ns[4],ns[5],ns[6],ns[7]);
                *(float4*)&As[AIDX(nxt,1,skk,smb)]   = make_float4(nc[0],nc[1],nc[2],nc[3]);
                *(float4*)&As[AIDX(nxt,1,skk,smb+4)] = make_float4(nc[4],nc[5],nc[6],nc[7]);

                // stage B(k=t+2) into buf nxt
                const float* g0 = fc + (size_t)(t + 1) * GSLAB + (size_t)ib * 512 + n0 + 4 * bn4;
#pragma unroll
                for (int r = 0; r < 8; ++r) {
                    int kk = 2 * r + bkk;
                    cpa16(bs_sa + BIDX(nxt,0,kk,4*bn4) * 4, g0 + (size_t)kk * 512);
                    cpa16(bs_sa + BIDX(nxt,1,kk,4*bn4) * 4, g0 + (size_t)kk * 512 + COFF);
                }
                asm volatile("cp.async.commit_group;");
                asm volatile("cp.async.wait_group 1;");
            } else {
                asm volatile("cp.async.wait_group 0;");
            }
            __syncthreads();

            // ---- GEMM over 16 kk of buf cur ----
            const float* aS = &As[AIDX(cur,0,0,w*16)];
            const float* aC = &As[AIDX(cur,1,0,w*16)];
            const char*  bS = (const char*)&Bs[BIDX(cur,0,0,0)] + l * 16;
            const char*  bC = (const char*)&Bs[BIDX(cur,1,0,0)] + l * 16;
#pragma unroll 2
            for (int kk = 0; kk < 16; ++kk) {
                {
                    float4 A0 = *(const float4*)(aS + kk*64);
                    float4 A1 = *(const float4*)(aS + kk*64 + 4);
                    float4 A2 = *(const float4*)(aS + kk*64 + 8);
                    float4 A3 = *(const float4*)(aS + kk*64 + 12);
                    float af[16] = {A0.x,A0.y,A0.z,A0.w,A1.x,A1.y,A1.z,A1.w,
                                    A2.x,A2.y,A2.z,A2.w,A3.x,A3.y,A3.z,A3.w};
                    ulonglong2 b0 = *(const ulonglong2*)(bS + kk*1024);
                    ulonglong2 b1 = *(const ulonglong2*)(bS + kk*1024 + 512);
#pragma unroll
                    for (int mi = 0; mi < 16; ++mi) {
                        unsigned long long ad = pk2(af[mi]);
                        fma2(acc[mi][0], ad, b0.x); fma2(acc[mi][1], ad, b0.y);
                        fma2(acc[mi][2], ad, b1.x); fma2(acc[mi][3], ad, b1.y);
                    }
                }
                {
                    float4 A0 = *(const float4*)(aC + kk*64);
                    float4 A1 = *(const float4*)(aC + kk*64 + 4);
                    float4 A2 = *(const float4*)(aC + kk*64 + 8);
                    float4 A3 = *(const float4*)(aC + kk*64 + 12);
                    float af[16] = {A0.x,A0.y,A0.z,A0.w,A1.x,A1.y,A1.z,A1.w,
                                    A2.x,A2.y,A2.z,A2.w,A3.x,A3.y,A3.z,A3.w};
                    ulonglong2 b0 = *(const ulonglong2*)(bC + kk*1024);
                    ulonglong2 b1 = *(const ulonglong2*)(bC + kk*1024 + 512);
#pragma unroll
                    for (int mi = 0; mi < 16; ++mi) {
                        unsigned long long ad = pk2(af[mi]);
                        fma2(acc[mi][0], ad, b0.x); fma2(acc[mi][1], ad, b0.y);
                        fma2(acc[mi][2], ad, b1.x); fma2(acc[mi][3], ad, b1.y);
                    }
                }
            }
            __syncthreads();
        }
    }

    // ---- epilogue: accumulate partials ----
#pragma unroll
    for (int mi = 0; mi < 16; ++mi) {
        float* op = out + (size_t)(m0 + w * 16 + mi) * 512 + n0;
        float2 v;
        v = upk(acc[mi][0]); atomicAdd(op + 4*l,       v.x); atomicAdd(op + 4*l + 1,   v.y);
        v = upk(acc[mi][1]); atomicAdd(op + 4*l + 2,   v.x); atomicAdd(op + 4*l + 3,   v.y);
        v = upk(acc[mi][2]); atomicAdd(op + 128 + 4*l,     v.x); atomicAdd(op + 128 + 4*l + 1, v.y);
        v = upk(acc[mi][3]); atomicAdd(op + 128 + 4*l + 2, v.x); atomicAdd(op + 128 + 4*l + 3, v.y);
    }
}

extern "C" void kernel_launch(void* const* d_in, const int* in_sizes, int n_in,
                              void* d_out, int out_size) {
    const float* x    = (const float*)d_in[0];
    const float* fc   = (const float*)d_in[1];
    const float* bias = (const float*)d_in[2];
    float* out = (float*)d_out;

    cudaFuncSetAttribute(fkan_kernel, cudaFuncAttributeMaxDynamicSharedMemorySize, SMEM_BYTES);

    init_out_kernel<<<4096, 256>>>(bias, out);       // out = bias (2048*512 = 1M elems)
    fkan_kernel<<<1024, 128, SMEM_BYTES>>>(x, fc, out);
}

// round 6
// speedup vs baseline: 1.0001x; 1.0001x over previous
#include <cuda_runtime.h>
#include <cstdint>

#define GSLAB 262144          // 512*512 floats per k-slab
#define COFF  (50*GSLAB)      // offset of cos slabs
#define AS_F  (2*2*16*64)     // A smem floats: [buf][feat][kk][64]
#define BS_F  (2*2*16*256)    // B smem floats: [buf][feat][kk][256]
#define SMEM_BYTES ((AS_F + BS_F) * 4)

#define AIDX(b,f,kk,m) ((((b)*2+(f))*16+(kk))*64+(m))
#define BIDX(b,f,kk,n) ((((b)*2+(f))*16+(kk))*256+(n))

__device__ __forceinline__ unsigned long long pk2(float v) {
    unsigned long long r; asm("mov.b64 %0, {%1, %1};" : "=l"(r) : "f"(v)); return r;
}
__device__ __forceinline__ float2 upk(unsigned long long v) {
    float2 r; asm("mov.b64 {%0, %1}, %2;" : "=f"(r.x), "=f"(r.y) : "l"(v)); return r;
}
__device__ __forceinline__ void fma2(unsigned long long& d, unsigned long long a, unsigned long long b) {
    asm("fma.rn.f32x2 %0, %1, %2, %0;" : "+l"(d) : "l"(a), "l"(b));
}
__device__ __forceinline__ void cpa16(uint32_t s, const float* g) {
    asm volatile("cp.async.cg.shared.global [%0], [%1], 16;" :: "r"(s), "l"(g));
}

__global__ void init_out_kernel(const float* __restrict__ bias, float* __restrict__ out) {
    int i = blockIdx.x * 256 + threadIdx.x;
    out[i] = bias[i & 511];
}

__global__ void __launch_bounds__(128, 2)
fkan_kernel(const float* __restrict__ x, const float* __restrict__ fc,
            float* __restrict__ out)
{
    extern __shared__ float sm[];
    float* As = sm;
    float* Bs = sm + AS_F;
    const uint32_t bs_sa = (uint32_t)__cvta_generic_to_shared(Bs);

    const int tid = threadIdx.x;
    const int w = tid >> 5, l = tid & 31;

    const int bid    = blockIdx.x;
    const int isplit = bid & 15;             // 16 i-splits of 32
    const int tile   = bid >> 4;             // 64 output tiles
    const int n0     = (tile & 1) * 256;
    const int m0     = (tile >> 1) * 64;

    // state slots: this thread owns (kk=skk, m=smb..smb+7)
    const int skk = tid >> 3;
    const int smb = (tid & 7) << 3;

    // B cp.async mapping: float4 f = r*128+tid -> kk = 2r + (tid>>6), n4 = tid&63
    const int bkk = tid >> 6;
    const int bn4 = tid & 63;

    unsigned long long acc[16][4];
#pragma unroll
    for (int i = 0; i < 16; ++i)
#pragma unroll
        for (int j = 0; j < 4; ++j) acc[i][j] = 0ull;

    for (int ic = 0; ic < 2; ++ic) {
        const int ib = isplit * 32 + ic * 16;

        // ---- base rotation (k=1): s1=sin(pi x), c1=cos(pi x); also initial state ----
        float s1[8], c1[8];
        const float* xp = x + (size_t)(m0 + smb) * 512 + ib + skk;
#pragma unroll
        for (int j = 0; j < 8; ++j) sincospif(__ldg(xp + (size_t)j * 512), &s1[j], &c1[j]);
        *(float4*)&As[AIDX(0,0,skk,smb)]   = make_float4(s1[0],s1[1],s1[2],s1[3]);
        *(float4*)&As[AIDX(0,0,skk,smb+4)] = make_float4(s1[4],s1[5],s1[6],s1[7]);
        *(float4*)&As[AIDX(0,1,skk,smb)]   = make_float4(c1[0],c1[1],c1[2],c1[3]);
        *(float4*)&As[AIDX(0,1,skk,smb+4)] = make_float4(c1[4],c1[5],c1[6],c1[7]);

        // ---- prologue: stage B(k=1) into buf 0 ----
        {
            const float* g0 = fc + (size_t)ib * 512 + n0 + 4 * bn4;
#pragma unroll
            for (int r = 0; r < 8; ++r) {
                int kk = 2 * r + bkk;
                cpa16(bs_sa + BIDX(0,0,kk,4*bn4) * 4, g0 + (size_t)kk * 512);
                cpa16(bs_sa + BIDX(0,1,kk,4*bn4) * 4, g0 + (size_t)kk * 512 + COFF);
            }
            asm volatile("cp.async.commit_group;");
        }

        for (int t = 0; t < 50; ++t) {
            const int cur = t & 1, nxt = cur ^ 1;

            if (t < 49) {
                // advance state: read k=t+1 from As[cur], write k=t+2 to As[nxt]
                float4 ps0 = *(float4*)&As[AIDX(cur,0,skk,smb)];
                float4 ps1 = *(float4*)&As[AIDX(cur,0,skk,smb+4)];
                float4 pc0 = *(float4*)&As[AIDX(cur,1,skk,smb)];
                float4 pc1 = *(float4*)&As[AIDX(cur,1,skk,smb+4)];
                float ps[8] = {ps0.x,ps0.y,ps0.z,ps0.w,ps1.x,ps1.y,ps1.z,ps1.w};
                float pc[8] = {pc0.x,pc0.y,pc0.z,pc0.w,pc1.x,pc1.y,pc1.z,pc1.w};
                float ns[8], nc[8];
#pragma unroll
                for (int j = 0; j < 8; ++j) {
                    ns[j] = fmaf(ps[j], c1[j],  pc[j] * s1[j]);
                    nc[j] = fmaf(pc[j], c1[j], -ps[j] * s1[j]);
                }
                *(float4*)&As[AIDX(nxt,0,skk,smb)]   = make_float4(ns[0],ns[1],ns[2],ns[3]);
                *(float4*)&As[AIDX(nxt,0,skk,smb+4)] = make_float4(ns[4],ns[5],ns[6],ns[7]);
                *(float4*)&As[AIDX(nxt,1,skk,smb)]   = make_float4(nc[0],nc[1],nc[2],nc[3]);
                *(float4*)&As[AIDX(nxt,1,skk,smb+4)] = make_float4(nc[4],nc[5],nc[6],nc[7]);

                // stage B(k=t+2) into buf nxt
                const float* g0 = fc + (size_t)(t + 1) * GSLAB + (size_t)ib * 512 + n0 + 4 * bn4;
#pragma unroll
                for (int r = 0; r < 8; ++r) {
                    int kk = 2 * r + bkk;
                    cpa16(bs_sa + BIDX(nxt,0,kk,4*bn4) * 4, g0 + (size_t)kk * 512);
                    cpa16(bs_sa + BIDX(nxt,1,kk,4*bn4) * 4, g0 + (size_t)kk * 512 + COFF);
                }
                asm volatile("cp.async.commit_group;");
                asm volatile("cp.async.wait_group 1;");
            } else {
                asm volatile("cp.async.wait_group 0;");
            }
            __syncthreads();

            // ---- GEMM over 16 kk of buf cur ----
            const float* aS = &As[AIDX(cur,0,0,w*16)];
            const float* aC = &As[AIDX(cur,1,0,w*16)];
            const char*  bS = (const char*)&Bs[BIDX(cur,0,0,0)] + l * 16;
            const char*  bC = (const char*)&Bs[BIDX(cur,1,0,0)] + l * 16;
#pragma unroll 2
            for (int kk = 0; kk < 16; ++kk) {
                {
                    float4 A0 = *(const float4*)(aS + kk*64);
                    float4 A1 = *(const float4*)(aS + kk*64 + 4);
                    float4 A2 = *(const float4*)(aS + kk*64 + 8);
                    float4 A3 = *(const float4*)(aS + kk*64 + 12);
                    float af[16] = {A0.x,A0.y,A0.z,A0.w,A1.x,A1.y,A1.z,A1.w,
                                    A2.x,A2.y,A2.z,A2.w,A3.x,A3.y,A3.z,A3.w};
                    ulonglong2 b0 = *(const ulonglong2*)(bS + kk*1024);
                    ulonglong2 b1 = *(const ulonglong2*)(bS + kk*1024 + 512);
#pragma unroll
                    for (int mi = 0; mi < 16; ++mi) {
                        unsigned long long ad = pk2(af[mi]);
                        fma2(acc[mi][0], ad, b0.x); fma2(acc[mi][1], ad, b0.y);
                        fma2(acc[mi][2], ad, b1.x); fma2(acc[mi][3], ad, b1.y);
                    }
                }
                {
                    float4 A0 = *(const float4*)(aC + kk*64);
                    float4 A1 = *(const float4*)(aC + kk*64 + 4);
                    float4 A2 = *(const float4*)(aC + kk*64 + 8);
                    float4 A3 = *(const float4*)(aC + kk*64 + 12);
                    float af[16] = {A0.x,A0.y,A0.z,A0.w,A1.x,A1.y,A1.z,A1.w,
                                    A2.x,A2.y,A2.z,A2.w,A3.x,A3.y,A3.z,A3.w};
                    ulonglong2 b0 = *(const ulonglong2*)(bC + kk*1024);
                    ulonglong2 b1 = *(const ulonglong2*)(bC + kk*1024 + 512);
#pragma unroll
                    for (int mi = 0; mi < 16; ++mi) {
                        unsigned long long ad = pk2(af[mi]);
                        fma2(acc[mi][0], ad, b0.x); fma2(acc[mi][1], ad, b0.y);
                        fma2(acc[mi][2], ad, b1.x); fma2(acc[mi][3], ad, b1.y);
                    }
                }
            }
            __syncthreads();
        }
    }

    // ---- epilogue: accumulate partials ----
#pragma unroll
    for (int mi = 0; mi < 16; ++mi) {
        float* op = out + (size_t)(m0 + w * 16 + mi) * 512 + n0;
        float2 v;
        v = upk(acc[mi][0]); atomicAdd(op + 4*l,       v.x); atomicAdd(op + 4*l + 1,   v.y);
        v = upk(acc[mi][1]); atomicAdd(op + 4*l + 2,   v.x); atomicAdd(op + 4*l + 3,   v.y);
        v = upk(acc[mi][2]); atomicAdd(op + 128 + 4*l,     v.x); atomicAdd(op + 128 + 4*l + 1, v.y);
        v = upk(acc[mi][3]); atomicAdd(op + 128 + 4*l + 2, v.x); atomicAdd(op + 128 + 4*l + 3, v.y);
    }
}

extern "C" void kernel_launch(void* const* d_in, const int* in_sizes, int n_in,
                              void* d_out, int out_size) {
    const float* x    = (const float*)d_in[0];
    const float* fc   = (const float*)d_in[1];
    const float* bias = (const float*)d_in[2];
    float* out = (float*)d_out;

    cudaFuncSetAttribute(fkan_kernel, cudaFuncAttributeMaxDynamicSharedMemorySize, SMEM_BYTES);

    init_out_kernel<<<4096, 256>>>(bias, out);       // out = bias (2048*512 = 1M elems)
    fkan_kernel<<<1024, 128, SMEM_BYTES>>>(x, fc, out);
}

// round 8
// speedup vs baseline: 2.0404x; 2.0402x over previous
#include <cuda_runtime.h>
#include <cstdint>

#define BST 136
#define BBUF (32*BST)                         // floats per B buffer
#define SMEM_BYTES (2*1024*16 + 2*BBUF*4)     // 32768 + 34816 = 67584

__device__ float g_fcT[26214400];             // tf32-rounded coeffs, same layout as fc

__device__ __forceinline__ uint32_t f2tf(float f){
    uint32_t u; asm("cvt.rna.tf32.f32 %0, %1;" : "=r"(u) : "f"(f)); return u;
}
__device__ __forceinline__ void mma8(float* d, const uint4 a, uint32_t b0, uint32_t b1){
    asm volatile("mma.sync.aligned.m16n8k8.row.col.f32.tf32.tf32.f32 "
        "{%0,%1,%2,%3}, {%4,%5,%6,%7}, {%8,%9}, {%0,%1,%2,%3};"
        : "+f"(d[0]),"+f"(d[1]),"+f"(d[2]),"+f"(d[3])
        : "r"(a.x),"r"(a.y),"r"(a.z),"r"(a.w), "r"(b0),"r"(b1));
}
__device__ __forceinline__ void cpa16(uint32_t s, const float* g){
    asm volatile("cp.async.cg.shared.global [%0], [%1], 16;" :: "r"(s), "l"(g));
}

__global__ void init_out_kernel(const float* __restrict__ bias, float* __restrict__ out){
    int i = blockIdx.x*256 + threadIdx.x;
    out[i] = bias[i & 511];
}

__global__ void prep_kernel(const float* __restrict__ fc){
    size_t i = ((size_t)blockIdx.x*256 + threadIdx.x)*4;
    float4 v = *(const float4*)(fc + i);
    uint4 u = make_uint4(f2tf(v.x), f2tf(v.y), f2tf(v.z), f2tf(v.w));
    *(uint4*)(g_fcT + i) = u;
}

struct Gen { float ss[8], cc[8], s1[8], c1[8]; };

__device__ __forceinline__ void init_state(Gen& G, const float* __restrict__ x,
                                            int m0, int MT_A, int gq, int ib, int ii0){
#pragma unroll
    for (int mq=0; mq<2; ++mq){
        int m = m0 + 16*(MT_A+4*mq) + gq;
#pragma unroll
        for (int mh=0; mh<2; ++mh)
#pragma unroll
        for (int iv=0; iv<2; ++iv){
            int j = mq*4 + mh*2 + iv;
            float xv = x[(size_t)(m + 8*mh)*512 + ib + ii0 + 4*iv];
            sincospif(xv, &G.s1[j], &G.c1[j]);
            G.ss[j] = G.s1[j]; G.cc[j] = G.c1[j];
        }
    }
}
__device__ __forceinline__ void advance(Gen& G){
#pragma unroll
    for (int j=0;j<8;++j){
        float ns = fmaf(G.ss[j], G.c1[j],  G.cc[j]*G.s1[j]);
        float nc = fmaf(G.cc[j], G.c1[j], -G.ss[j]*G.s1[j]);
        G.ss[j]=ns; G.cc[j]=nc;
    }
}
// A fragments: Af[buf][MT(8)][kt(4)][lane(32)] as uint4 {a0,a1,a2,a3}
__device__ __forceinline__ void write_af(uint4* Af, int buf, int MT_A, int kts, int lw, const Gen& G){
    const int xl = lw ^ (4*(kts&1));
#pragma unroll
    for (int mq=0; mq<2; ++mq){
        int base = mq*4;
        int idx = buf*1024 + (MT_A + 4*mq)*128 + xl;
        Af[idx + kts*32]     = make_uint4(f2tf(G.ss[base+0]), f2tf(G.ss[base+2]),
                                          f2tf(G.ss[base+1]), f2tf(G.ss[base+3]));
        Af[idx + (kts+2)*32] = make_uint4(f2tf(G.cc[base+0]), f2tf(G.cc[base+2]),
                                          f2tf(G.cc[base+1]), f2tf(G.cc[base+3]));
    }
}

__global__ void __launch_bounds__(256,1)
fkan_mma(const float* __restrict__ x, float* __restrict__ out)
{
    extern __shared__ char smem[];
    uint4* Af = (uint4*)smem;
    float* Bs = (float*)(smem + 2*1024*16);
    const uint32_t bs_sa = (uint32_t)__cvta_generic_to_shared(Bs);

    const int tid  = threadIdx.x;
    const int lane = tid & 31;
    const int wid  = tid >> 5;
    const int gid  = lane >> 2, tig = lane & 3;
    const int wm   = wid >> 2,  wn  = wid & 3;

    const int m0 = blockIdx.x*128, n0 = blockIdx.y*128, ibase = blockIdx.z*128;

    // generator decomposition: thread owns 2 quads of (m,m+8)x(ii0,ii0+4)
    const int MT_A = tid>>6;
    const int gq   = (tid>>3)&7;
    const int iq   = tid&7;
    const int ii0  = ((iq>>2)<<3)|(iq&3);
    const int lw   = 4*gq + (iq&3);
    const int kts  = ii0>>3;

    // B cp.async mapping: 32 rows(k) x 128 floats(n) per buffer, 4 x 16B per thread
    const float* bsrc[4]; uint32_t bdst[4];
#pragma unroll
    for (int q=0;q<4;++q){
        int c = q*256+tid, row = c>>5, col4 = c&31;
        int f = row>>4, ii = row&15;
        bsrc[q] = g_fcT + (size_t)f*13107200 + (size_t)(ibase+ii)*512 + n0 + 4*col4;
        bdst[q] = bs_sa + (uint32_t)(row*BST + 4*col4)*4;
    }

    float acc[4][4][4];
#pragma unroll
    for (int a=0;a<4;++a)
#pragma unroll
    for (int b=0;b<4;++b)
#pragma unroll
    for (int c=0;c<4;++c) acc[a][b][c]=0.f;

    Gen G;
    init_state(G, x, m0, MT_A, gq, ibase, ii0);
    write_af(Af, 0, MT_A, kts, lw, G);
#pragma unroll
    for (int q=0;q<4;++q) cpa16(bdst[q], bsrc[q]);
    asm volatile("cp.async.commit_group;");

    int t = 0;
    for (int chunk=0; chunk<8; ++chunk){
        for (int gI=0; gI<50; ++gI, ++t){
            const int cur = t&1, nxt = cur^1;
            const bool hn = (t < 399);
            if (hn){
                if (gI < 49) advance(G);
                else init_state(G, x, m0, MT_A, gq, ibase + (chunk+1)*16, ii0);
            }
            asm volatile("cp.async.wait_group 0;");
            __syncthreads();
            if (hn){
                int gN = (gI<49)? gI+1 : 0;
                int cN = (gI<49)? chunk : chunk+1;
                size_t go = (size_t)gN*262144 + (size_t)cN*8192;
#pragma unroll
                for (int q=0;q<4;++q) cpa16(bdst[q] + nxt*(BBUF*4), bsrc[q]+go);
                asm volatile("cp.async.commit_group;");
                write_af(Af, nxt, MT_A, kts, lw, G);
            }
            // ---- 64 mma per warp over the 32-wide K slice ----
            const uint4* Aw = Af + cur*1024 + wm*512;
            const float* Bw = Bs + cur*BBUF + wn*32;
#pragma unroll
            for (int kt=0; kt<4; ++kt){
                const int xo = 4*(kt&1);
                uint4 a[4];
#pragma unroll
                for (int mt=0;mt<4;++mt) a[mt] = Aw[mt*128 + kt*32 + (lane ^ xo)];
#pragma unroll
                for (int nt=0;nt<4;++nt){
                    uint32_t b0 = __float_as_uint(Bw[(kt*8+tig)*BST   + nt*8 + gid]);
                    uint32_t b1 = __float_as_uint(Bw[(kt*8+tig+4)*BST + nt*8 + gid]);
#pragma unroll
                    for (int mt=0;mt<4;++mt) mma8(acc[mt][nt], a[mt], b0, b1);
                }
            }
        }
    }

    // ---- epilogue: accumulate split-K partials ----
#pragma unroll
    for (int mt=0;mt<4;++mt)
#pragma unroll
    for (int nt=0;nt<4;++nt){
        float* op = out + (size_t)(m0 + wm*64 + mt*16 + gid)*512 + n0 + wn*32 + nt*8 + 2*tig;
        atomicAdd(op,      acc[mt][nt][0]);
        atomicAdd(op+1,    acc[mt][nt][1]);
        atomicAdd(op+4096, acc[mt][nt][2]);   // +8 rows * 512
        atomicAdd(op+4097, acc[mt][nt][3]);
    }
}

extern "C" void kernel_launch(void* const* d_in, const int* in_sizes, int n_in,
                              void* d_out, int out_size) {
    const float* x    = (const float*)d_in[0];
    const float* fc   = (const float*)d_in[1];
    const float* bias = (const float*)d_in[2];
    float* out = (float*)d_out;

    cudaFuncSetAttribute(fkan_mma, cudaFuncAttributeMaxDynamicSharedMemorySize, SMEM_BYTES);

    init_out_kernel<<<4096, 256>>>(bias, out);
    prep_kernel<<<25600, 256>>>(fc);
    fkan_mma<<<dim3(16,4,4), 256, SMEM_BYTES>>>(x, out);
}